// round 8
// baseline (speedup 1.0000x reference)
#include <cuda_runtime.h>

// MedianFilter: xs [B=4,T=32,N=128,D=32] f32, A [1,128,128] i32.
// Per (b,t,n,d): lower median over {prev-self (t>0), next-self (t<T-1),
//   xs[b,t,j,d] for j with (A+I)[n][j]!=0}.
//
// Shared-sort + bitmask rank selection (exact), ILP-restructured:
//  - per (bt, channel): bitonic-sort 128 frame values once (warp per channel,
//    carrying row index); cum[i] = 128-bit mask of rows at sorted pos < i,
//    stored as 4 SoA planes with XOR bank swizzle (conflict-free).
//  - per node: median = 7-step binary search with popc(B & cum[c]); temporal
//    prev/next ranked via value binary-search. All searches for the warp's
//    4 nodes run step-major (8 then 4 independent chains) for ILP.
//  - prev/next frames staged into shared in phase 0 (no GMEM in phase 2).

#define Bc 4
#define Tc 32
#define Nc 128
#define Dc 32
#define NTH 1024

typedef unsigned u32;

// dynamic smem word layout:
//  [0, 16512)       cum planes: 4 x 4128 (swizzled [i][ch]); phase 0 aliases
//                   the first 4256 words as the current-frame tile (stride 33)
//  [16512, 20640)   sorted keys: 32 channels x 129
//  [20640, 21152)   Bmask: 128 x uint4
//  [21152, 25248)   prev-frame tile [n][ch] (0xFFFFFFFF when t==0)
//  [25248, 29344)   next-frame tile [n][ch] (0xFFFFFFFF when t==T-1)
extern __shared__ u32 smem[];
#define PLS       4128
#define SORT_BASE 16512
#define BM_BASE   20640
#define PT_BASE   21152
#define NX_BASE   25248
#define SMEM_WORDS 29344

__device__ __forceinline__ u32 f2u(float f) {
    u32 s = __float_as_uint(f);
    return s ^ ((u32)((int)s >> 31) | 0x80000000u);
}
__device__ __forceinline__ float u2f(u32 u) {
    u32 s = (u & 0x80000000u) ? (u ^ 0x80000000u) : ~u;
    return __uint_as_float(s);
}

// # of B-members at sorted positions < c (planes are XOR-swizzled)
__device__ __forceinline__ int plane_popc(uint4 B, int ch, int c) {
    int base = c * 32 + (ch ^ (c & 31));
    u32 c0 = smem[base];
    u32 c1 = smem[PLS + base];
    u32 c2 = smem[2 * PLS + base];
    u32 c3 = smem[3 * PLS + base];
    return __popc(B.x & c0) + __popc(B.y & c1)
         + __popc(B.z & c2) + __popc(B.w & c3);
}

__global__ __launch_bounds__(NTH, 1)
void median_kernel(const float* __restrict__ xs,
                   const int* __restrict__ A,
                   float* __restrict__ out)
{
    const int bt   = blockIdx.x;
    const int t    = bt & (Tc - 1);
    const int tid  = threadIdx.x;
    const int lane = tid & 31;
    const int w    = tid >> 5;

    const bool hasPrev = (t > 0);
    const bool hasNext = (t < Tc - 1);

    // ---------------- phase 0: stage three frames + adjacency masks ---------
    const float* cur = xs + (size_t)bt * (Nc * Dc);
    #pragma unroll
    for (int i = tid; i < Nc * Dc; i += NTH)
        smem[(i >> 5) * 33 + (i & 31)] = f2u(cur[i]);   // aliased tile

    {   // prev/next tiles, vectorized (one uint4 per thread)
        const uint4* pv4 = (const uint4*)(xs + (size_t)(bt - 1) * (Nc * Dc));
        const uint4* nx4 = (const uint4*)(xs + (size_t)(bt + 1) * (Nc * Dc));
        uint4 p = make_uint4(~0u, ~0u, ~0u, ~0u), q = p;
        if (hasPrev) {
            uint4 v = pv4[tid];
            p = make_uint4(f2u(__uint_as_float(v.x)), f2u(__uint_as_float(v.y)),
                           f2u(__uint_as_float(v.z)), f2u(__uint_as_float(v.w)));
        }
        if (hasNext) {
            uint4 v = nx4[tid];
            q = make_uint4(f2u(__uint_as_float(v.x)), f2u(__uint_as_float(v.y)),
                           f2u(__uint_as_float(v.z)), f2u(__uint_as_float(v.w)));
        }
        ((uint4*)(smem + PT_BASE))[tid] = p;
        ((uint4*)(smem + NX_BASE))[tid] = q;
    }

    if (tid < 512) {                              // Bmask: 4 threads per node
        int n = tid >> 2, ww = tid & 3;
        const int* ar = A + n * Nc + ww * 32;
        u32 b = 0;
        #pragma unroll 8
        for (int jj = 0; jj < 32; jj++) b |= (ar[jj] != 0 ? 1u : 0u) << jj;
        if ((n >> 5) == ww) b |= 1u << (n & 31);  // + I (self loop)
        smem[BM_BASE + n * 4 + ww] = b;
    }
    __syncthreads();

    // ---------------- phase 1: per-channel sort + cum planes ----------------
    u32 k[4], xi[4];
    #pragma unroll
    for (int r = 0; r < 4; r++) {
        int p = r * 32 + lane;
        k[r]  = smem[p * 33 + w];
        xi[r] = (u32)p;
    }
    __syncthreads();    // tile reads done before cum planes overwrite region

    #pragma unroll
    for (int size = 2; size <= 128; size <<= 1) {
        #pragma unroll
        for (int stride = size >> 1; stride > 0; stride >>= 1) {
            if (stride >= 32) {
                int sr = stride >> 5;
                #pragma unroll
                for (int r = 0; r < 4; r++) {
                    if (!(r & sr)) {
                        int r2 = r | sr;
                        bool up = (((r * 32) & size) == 0);
                        if ((k[r] > k[r2]) == up) {
                            u32 tk = k[r]; k[r] = k[r2]; k[r2] = tk;
                            u32 tx = xi[r]; xi[r] = xi[r2]; xi[r2] = tx;
                        }
                    }
                }
            } else {
                #pragma unroll
                for (int r = 0; r < 4; r++) {
                    u32 p = (u32)(r * 32 + lane);
                    bool up    = ((p & (u32)size) == 0);
                    bool lower = ((lane & stride) == 0);
                    u32 pk = __shfl_xor_sync(0xFFFFFFFFu, k[r],  stride);
                    u32 px = __shfl_xor_sync(0xFFFFFFFFu, xi[r], stride);
                    bool take = (lower == up) ? (pk < k[r]) : (pk > k[r]);
                    if (take) { k[r] = pk; xi[r] = px; }
                }
            }
        }
    }

    #pragma unroll
    for (int r = 0; r < 4; r++)
        smem[SORT_BASE + w * 129 + r * 32 + lane] = k[r];

    // cum[i] = OR of onehot(orig row) over sorted positions < i, into planes
    {
        u32 run0 = 0, run1 = 0, run2 = 0, run3 = 0;
        #pragma unroll
        for (int r = 0; r < 4; r++) {
            int ws = (int)(xi[r] >> 5);
            u32 bit = 1u << (xi[r] & 31u);
            u32 o0 = (ws == 0) ? bit : 0u, o1 = (ws == 1) ? bit : 0u;
            u32 o2 = (ws == 2) ? bit : 0u, o3 = (ws == 3) ? bit : 0u;
            #pragma unroll
            for (int s = 1; s < 32; s <<= 1) {
                u32 t0 = __shfl_up_sync(0xFFFFFFFFu, o0, s);
                u32 t1 = __shfl_up_sync(0xFFFFFFFFu, o1, s);
                u32 t2 = __shfl_up_sync(0xFFFFFFFFu, o2, s);
                u32 t3 = __shfl_up_sync(0xFFFFFFFFu, o3, s);
                if (lane >= s) { o0 |= t0; o1 |= t1; o2 |= t2; o3 |= t3; }
            }
            u32 e0 = __shfl_up_sync(0xFFFFFFFFu, o0, 1);
            u32 e1 = __shfl_up_sync(0xFFFFFFFFu, o1, 1);
            u32 e2 = __shfl_up_sync(0xFFFFFFFFu, o2, 1);
            u32 e3 = __shfl_up_sync(0xFFFFFFFFu, o3, 1);
            if (lane == 0) { e0 = 0; e1 = 0; e2 = 0; e3 = 0; }
            int p = r * 32 + lane;
            int base = p * 32 + (w ^ lane);          // (p & 31) == lane
            smem[base]           = run0 | e0;
            smem[PLS + base]     = run1 | e1;
            smem[2 * PLS + base] = run2 | e2;
            smem[3 * PLS + base] = run3 | e3;
            run0 |= __shfl_sync(0xFFFFFFFFu, o0, 31);
            run1 |= __shfl_sync(0xFFFFFFFFu, o1, 31);
            run2 |= __shfl_sync(0xFFFFFFFFu, o2, 31);
            run3 |= __shfl_sync(0xFFFFFFFFu, o3, 31);
        }
        if (lane == 0) {
            int base = 128 * 32 + w;                 // (128 & 31) == 0
            smem[base] = ~0u; smem[PLS + base] = ~0u;
            smem[2 * PLS + base] = ~0u; smem[3 * PLS + base] = ~0u;
        }
    }
    __syncthreads();

    // ---------------- phase 2: step-major median selection ------------------
    // warp w handles nodes w, w+32, w+64, w+96; lane = channel.
    const int ch = lane;

    uint4 Bm[4];
    u32 pv[4], nv[4];
    int m4[4];
    #pragma unroll
    for (int nn = 0; nn < 4; nn++) {
        const int n = w + nn * 32;
        Bm[nn] = *((const uint4*)(smem + BM_BASE + n * 4));   // broadcast
        pv[nn] = smem[PT_BASE + n * 32 + ch];
        nv[nn] = smem[NX_BASE + n * 32 + ch];
        int kpop = __popc(Bm[nn].x) + __popc(Bm[nn].y)
                 + __popc(Bm[nn].z) + __popc(Bm[nn].w);
        m4[nn] = (kpop + (int)hasPrev + (int)hasNext - 1) >> 1;
    }

    // 8 interleaved value binary-searches: ub = #sorted keys <= v
    int ubp[4] = {0, 0, 0, 0}, ubn[4] = {0, 0, 0, 0};
    #pragma unroll
    for (int st = 128; st > 0; st >>= 1) {
        #pragma unroll
        for (int nn = 0; nn < 4; nn++) {
            int c = ubp[nn] + st;
            if (c <= 128 && smem[SORT_BASE + ch * 129 + c - 1] <= pv[nn]) ubp[nn] = c;
            int c2 = ubn[nn] + st;
            if (c2 <= 128 && smem[SORT_BASE + ch * 129 + c2 - 1] <= nv[nn]) ubn[nn] = c2;
        }
    }

    // ranks of temporal candidates (members first on value ties; prev < next)
    int rp4[4], rn4[4], j4[4];
    #pragma unroll
    for (int nn = 0; nn < 4; nn++) {
        rp4[nn] = plane_popc(Bm[nn], ch, ubp[nn]) + (int)(nv[nn] <  pv[nn]);
        rn4[nn] = plane_popc(Bm[nn], ch, ubn[nn]) + (int)(pv[nn] <= nv[nn]);
        j4[nn]  = m4[nn] - (int)(rp4[nn] < m4[nn]) - (int)(rn4[nn] < m4[nn]);
    }

    // 4 interleaved mask binary-searches: largest i with #members(<i) <= j
    int ii[4] = {0, 0, 0, 0};
    #pragma unroll
    for (int st = 64; st > 0; st >>= 1) {
        #pragma unroll
        for (int nn = 0; nn < 4; nn++) {
            int c = ii[nn] + st;                    // <= 127
            int g = plane_popc(Bm[nn], ch, c);
            if (g <= j4[nn]) ii[nn] = c;
        }
    }

    #pragma unroll
    for (int nn = 0; nn < 4; nn++) {
        const int n = w + nn * 32;
        u32 ans = smem[SORT_BASE + ch * 129 + ii[nn]];
        if (rn4[nn] == m4[nn]) ans = nv[nn];
        if (rp4[nn] == m4[nn]) ans = pv[nn];
        out[(size_t)bt * (Nc * Dc) + n * Dc + ch] = u2f(ans);
    }
}

extern "C" void kernel_launch(void* const* d_in, const int* in_sizes, int n_in,
                              void* d_out, int out_size)
{
    const float* xs  = (const float*)d_in[0];
    const int*   A   = (const int*)d_in[1];
    float*       out = (float*)d_out;
    (void)in_sizes; (void)n_in; (void)out_size;

    const int dyn = SMEM_WORDS * 4;   // 117376 bytes
    cudaFuncSetAttribute(median_kernel,
                         cudaFuncAttributeMaxDynamicSharedMemorySize, dyn);
    cudaFuncSetAttribute(median_kernel,
                         cudaFuncAttributePreferredSharedMemoryCarveout, 100);
    median_kernel<<<Bc * Tc, NTH, dyn>>>(xs, A, out);
}

// round 9
// speedup vs baseline: 1.2192x; 1.2192x over previous
#include <cuda_runtime.h>

// MedianFilter: xs [B=4,T=32,N=128,D=32] f32, A [1,128,128] i32.
// Per (b,t,n,d): lower median over {prev-self (t>0), next-self (t<T-1),
//   xs[b,t,j,d] for j with (A+I)[n][j]!=0}.
//
// Shared-sort + bitmask rank selection (exact), fine-grained blocks:
//  block = (bt, 4 channels), 128 threads. Warp w sorts channel w (bitonic,
//  carrying row index), builds cum[c] = uint4 mask of rows at sorted pos < c.
//  Phase 2: warp w = node group w (lane = node); per channel: median via
//  7-step popc(B & cum[c]) binary search; temporal prev/next ranked by value
//  binary search. Adjacency masks precomputed once (ballot prep kernel).

#define Bc 4
#define Tc 32
#define NTOT 128
#define Dc 32
#define NTH 128          // 4 warps per block
#define CPB 4            // channels per block

typedef unsigned u32;

__device__ uint4 g_bm[NTOT];     // (A + I) row masks

__device__ __forceinline__ u32 f2u(float f) {
    u32 s = __float_as_uint(f);
    return s ^ ((u32)((int)s >> 31) | 0x80000000u);
}
__device__ __forceinline__ float u2f(u32 u) {
    u32 s = (u & 0x80000000u) ? (u ^ 0x80000000u) : ~u;
    return __uint_as_float(s);
}

__global__ void prep_kernel(const int* __restrict__ A)
{
    int gw   = (blockIdx.x * blockDim.x + threadIdx.x) >> 5;   // node
    int lane = threadIdx.x & 31;
    if (gw >= NTOT) return;
    const int* row = A + gw * NTOT;
    u32 m0 = __ballot_sync(0xFFFFFFFFu, row[lane]      != 0);
    u32 m1 = __ballot_sync(0xFFFFFFFFu, row[32 + lane] != 0);
    u32 m2 = __ballot_sync(0xFFFFFFFFu, row[64 + lane] != 0);
    u32 m3 = __ballot_sync(0xFFFFFFFFu, row[96 + lane] != 0);
    if (lane == 0) {
        u32 sb = 1u << (gw & 31);
        uint4 r = make_uint4(m0, m1, m2, m3);
        int ws = gw >> 5;
        if (ws == 0) r.x |= sb; else if (ws == 1) r.y |= sb;
        else if (ws == 2) r.z |= sb; else r.w |= sb;
        g_bm[gw] = r;
    }
}

__global__ __launch_bounds__(NTH, 7)
void median_kernel(const float* __restrict__ xs, float* __restrict__ out)
{
    __shared__ u32   tile[NTOT * 5];     // cur  [row][cl], pad-5 (bank-clean)
    __shared__ u32   pvt [NTOT * 5];     // prev [row][cl] (0xFFFFFFFF if t==0)
    __shared__ u32   nxt [NTOT * 5];     // next [row][cl] (0xFFFFFFFF if t==T-1)
    __shared__ u32   skey[CPB * 132];    // sorted keys per channel (129 used)
    __shared__ uint4 cum [CPB * 136];    // cum masks per channel (129 used)
    __shared__ uint4 bmask[NTOT];

    const int bid  = blockIdx.x;
    const int bt   = bid >> 3;           // frame
    const int cg   = bid & 7;            // channel group
    const int cbase = cg * CPB;
    const int t    = bt & (Tc - 1);
    const int tid  = threadIdx.x;
    const int lane = tid & 31;
    const int w    = tid >> 5;

    const bool hasPrev = (t > 0);
    const bool hasNext = (t < Tc - 1);

    // ---------------- phase 0: stage tiles + masks --------------------------
    {
        const uint4* b4 = (const uint4*)xs;      // frame = 1024 uint4
        const int off = tid * 8 + cg;            // row tid, channel quad cg
        uint4 v = b4[(size_t)bt * 1024 + off];
        tile[tid * 5 + 0] = f2u(__uint_as_float(v.x));
        tile[tid * 5 + 1] = f2u(__uint_as_float(v.y));
        tile[tid * 5 + 2] = f2u(__uint_as_float(v.z));
        tile[tid * 5 + 3] = f2u(__uint_as_float(v.w));
        uint4 p = make_uint4(~0u, ~0u, ~0u, ~0u), q = p;
        if (hasPrev) {
            uint4 x = b4[(size_t)(bt - 1) * 1024 + off];
            p = make_uint4(f2u(__uint_as_float(x.x)), f2u(__uint_as_float(x.y)),
                           f2u(__uint_as_float(x.z)), f2u(__uint_as_float(x.w)));
        }
        if (hasNext) {
            uint4 x = b4[(size_t)(bt + 1) * 1024 + off];
            q = make_uint4(f2u(__uint_as_float(x.x)), f2u(__uint_as_float(x.y)),
                           f2u(__uint_as_float(x.z)), f2u(__uint_as_float(x.w)));
        }
        pvt[tid * 5 + 0] = p.x; pvt[tid * 5 + 1] = p.y;
        pvt[tid * 5 + 2] = p.z; pvt[tid * 5 + 3] = p.w;
        nxt[tid * 5 + 0] = q.x; nxt[tid * 5 + 1] = q.y;
        nxt[tid * 5 + 2] = q.z; nxt[tid * 5 + 3] = q.w;
        bmask[tid] = g_bm[tid];
    }
    __syncthreads();

    // ---------------- phase 1: warp w sorts channel w + cum masks -----------
    u32 k[4], xi[4];
    #pragma unroll
    for (int r = 0; r < 4; r++) {
        int p = r * 32 + lane;
        k[r]  = tile[p * 5 + w];
        xi[r] = (u32)p;
    }

    #pragma unroll
    for (int size = 2; size <= 128; size <<= 1) {
        #pragma unroll
        for (int stride = size >> 1; stride > 0; stride >>= 1) {
            if (stride >= 32) {
                int sr = stride >> 5;
                #pragma unroll
                for (int r = 0; r < 4; r++) {
                    if (!(r & sr)) {
                        int r2 = r | sr;
                        bool up = (((r * 32) & size) == 0);
                        if ((k[r] > k[r2]) == up) {
                            u32 tk = k[r]; k[r] = k[r2]; k[r2] = tk;
                            u32 tx = xi[r]; xi[r] = xi[r2]; xi[r2] = tx;
                        }
                    }
                }
            } else {
                #pragma unroll
                for (int r = 0; r < 4; r++) {
                    u32 p = (u32)(r * 32 + lane);
                    bool up    = ((p & (u32)size) == 0);
                    bool lower = ((lane & stride) == 0);
                    u32 pk = __shfl_xor_sync(0xFFFFFFFFu, k[r],  stride);
                    u32 px = __shfl_xor_sync(0xFFFFFFFFu, xi[r], stride);
                    bool take = (lower == up) ? (pk < k[r]) : (pk > k[r]);
                    if (take) { k[r] = pk; xi[r] = px; }
                }
            }
        }
    }

    #pragma unroll
    for (int r = 0; r < 4; r++)
        skey[w * 132 + r * 32 + lane] = k[r];

    {   // cum[c] = OR of onehot(orig row) over sorted positions < c (exclusive)
        u32 run0 = 0, run1 = 0, run2 = 0, run3 = 0;
        #pragma unroll
        for (int r = 0; r < 4; r++) {
            int ws = (int)(xi[r] >> 5);
            u32 bit = 1u << (xi[r] & 31u);
            u32 o0 = (ws == 0) ? bit : 0u, o1 = (ws == 1) ? bit : 0u;
            u32 o2 = (ws == 2) ? bit : 0u, o3 = (ws == 3) ? bit : 0u;
            #pragma unroll
            for (int s = 1; s < 32; s <<= 1) {
                u32 t0 = __shfl_up_sync(0xFFFFFFFFu, o0, s);
                u32 t1 = __shfl_up_sync(0xFFFFFFFFu, o1, s);
                u32 t2 = __shfl_up_sync(0xFFFFFFFFu, o2, s);
                u32 t3 = __shfl_up_sync(0xFFFFFFFFu, o3, s);
                if (lane >= s) { o0 |= t0; o1 |= t1; o2 |= t2; o3 |= t3; }
            }
            u32 e0 = __shfl_up_sync(0xFFFFFFFFu, o0, 1);
            u32 e1 = __shfl_up_sync(0xFFFFFFFFu, o1, 1);
            u32 e2 = __shfl_up_sync(0xFFFFFFFFu, o2, 1);
            u32 e3 = __shfl_up_sync(0xFFFFFFFFu, o3, 1);
            if (lane == 0) { e0 = 0; e1 = 0; e2 = 0; e3 = 0; }
            int p = r * 32 + lane;
            cum[w * 136 + p] = make_uint4(run0 | e0, run1 | e1,
                                          run2 | e2, run3 | e3);
            run0 |= __shfl_sync(0xFFFFFFFFu, o0, 31);
            run1 |= __shfl_sync(0xFFFFFFFFu, o1, 31);
            run2 |= __shfl_sync(0xFFFFFFFFu, o2, 31);
            run3 |= __shfl_sync(0xFFFFFFFFu, o3, 31);
        }
        if (lane == 0)
            cum[w * 136 + 128] = make_uint4(~0u, ~0u, ~0u, ~0u);
    }
    __syncthreads();

    // ---------------- phase 2: warp w = node group w, lane = node -----------
    const int n = w * 32 + lane;
    const uint4 B = bmask[n];
    const int kpop = __popc(B.x) + __popc(B.y) + __popc(B.z) + __popc(B.w);
    const int m = (kpop + (int)hasPrev + (int)hasNext - 1) >> 1;

    u32 pv[4], nv[4];
    #pragma unroll
    for (int cl = 0; cl < CPB; cl++) {
        pv[cl] = pvt[n * 5 + cl];
        nv[cl] = nxt[n * 5 + cl];
    }

    // 8 interleaved value binary-searches: ub = #sorted keys <= v
    int ubp[4] = {0, 0, 0, 0}, ubn[4] = {0, 0, 0, 0};
    #pragma unroll
    for (int st = 128; st > 0; st >>= 1) {
        #pragma unroll
        for (int cl = 0; cl < CPB; cl++) {
            int c = ubp[cl] + st;
            if (c <= 128 && skey[cl * 132 + c - 1] <= pv[cl]) ubp[cl] = c;
            int c2 = ubn[cl] + st;
            if (c2 <= 128 && skey[cl * 132 + c2 - 1] <= nv[cl]) ubn[cl] = c2;
        }
    }

    // temporal ranks (members first on ties; prev before next on ties)
    int jj[4], rp[4], rn[4];
    #pragma unroll
    for (int cl = 0; cl < CPB; cl++) {
        uint4 cp = cum[cl * 136 + ubp[cl]];
        rp[cl] = __popc(B.x & cp.x) + __popc(B.y & cp.y)
               + __popc(B.z & cp.z) + __popc(B.w & cp.w) + (int)(nv[cl] < pv[cl]);
        uint4 cn = cum[cl * 136 + ubn[cl]];
        rn[cl] = __popc(B.x & cn.x) + __popc(B.y & cn.y)
               + __popc(B.z & cn.z) + __popc(B.w & cn.w) + (int)(pv[cl] <= nv[cl]);
        jj[cl] = m - (int)(rp[cl] < m) - (int)(rn[cl] < m);
    }

    // 4 interleaved mask binary-searches: largest i with #members(<i) <= j
    int ii[4] = {0, 0, 0, 0};
    #pragma unroll
    for (int st = 64; st > 0; st >>= 1) {
        #pragma unroll
        for (int cl = 0; cl < CPB; cl++) {
            int c = ii[cl] + st;                 // <= 127
            uint4 cm = cum[cl * 136 + c];
            int g = __popc(B.x & cm.x) + __popc(B.y & cm.y)
                  + __popc(B.z & cm.z) + __popc(B.w & cm.w);
            if (g <= jj[cl]) ii[cl] = c;
        }
    }

    #pragma unroll
    for (int cl = 0; cl < CPB; cl++) {
        u32 ans = skey[cl * 132 + ii[cl]];
        if (rn[cl] == m) ans = nv[cl];
        if (rp[cl] == m) ans = pv[cl];
        out[(size_t)bt * (NTOT * Dc) + n * Dc + cbase + cl] = u2f(ans);
    }
}

extern "C" void kernel_launch(void* const* d_in, const int* in_sizes, int n_in,
                              void* d_out, int out_size)
{
    const float* xs  = (const float*)d_in[0];
    const int*   A   = (const int*)d_in[1];
    float*       out = (float*)d_out;
    (void)in_sizes; (void)n_in; (void)out_size;

    cudaFuncSetAttribute(median_kernel,
                         cudaFuncAttributePreferredSharedMemoryCarveout, 100);
    prep_kernel<<<4, 1024>>>(A);
    median_kernel<<<Bc * Tc * 8, NTH>>>(xs, out);
}

// round 13
// speedup vs baseline: 1.3032x; 1.0689x over previous
#include <cuda_runtime.h>

// MedianFilter: xs [B=4,T=32,N=128,D=32] f32, A [1,128,128] i32.
// Per (b,t,n,d): lower median over {prev-self (t>0), next-self (t<T-1),
//   xs[b,t,j,d] for j with (A+I)[n][j]!=0}.
//
// Exact, search-free selection:
//  - warp per channel: bitonic-sort the 128 frame values (carrying row index)
//  - per node: P[n] = 128-bit membership mask permuted into sorted order,
//    built via warp-shuffle 32x32 bit transposes of C = (A+I)^T columns
//  - median: member order-stats M[m-2], M[m-1], M[m] via register select-bit
//    on P; prev/next resolved by the 5-candidate rank rule (no value search).

#define Bc 4
#define Tc 32
#define NTOT 128
#define Dc 32
#define NTH 128          // 4 warps per block
#define CPB 4            // channels per block
#define PSTR 17          // P row stride in words (odd -> conflict-free)

typedef unsigned u32;

__device__ u32 g_C[NTOT * 4];   // C[j].word[g]: bit n' = (A+I)[g*32+n'][j] != 0

__device__ __forceinline__ u32 f2u(float f) {
    u32 s = __float_as_uint(f);
    return s ^ ((u32)((int)s >> 31) | 0x80000000u);
}
__device__ __forceinline__ float u2f(u32 u) {
    u32 s = (u & 0x80000000u) ? (u ^ 0x80000000u) : ~u;
    return __uint_as_float(s);
}

// 32x32 bit-matrix transpose across a warp (lane = row, bits = cols)
__device__ __forceinline__ u32 transpose32(u32 x, int lane) {
    u32 y;
#define TSTEP(J, M)                                              \
    y = __shfl_xor_sync(0xFFFFFFFFu, x, J);                      \
    x = (lane & J) ? ((x & ~(M)) | ((y >> J) & (M)))             \
                   : ((x & (M)) | ((y & (M)) << J));
    TSTEP(16, 0x0000FFFFu)
    TSTEP(8,  0x00FF00FFu)
    TSTEP(4,  0x0F0F0F0Fu)
    TSTEP(2,  0x33333333u)
    TSTEP(1,  0x55555555u)
#undef TSTEP
    return x;
}

// position of q-th (0-based) set bit of v (q < popc(v))
__device__ __forceinline__ int sel_in_word(u32 v, int q) {
    int off = 0;
    int c;
    c = __popc(v & 0xFFFFu); if (q >= c) { q -= c; v >>= 16; off += 16; }
    c = __popc(v & 0xFFu);   if (q >= c) { q -= c; v >>= 8;  off += 8; }
    c = __popc(v & 0xFu);    if (q >= c) { q -= c; v >>= 4;  off += 4; }
    c = __popc(v & 0x3u);    if (q >= c) { q -= c; v >>= 2;  off += 2; }
    off += (int)(q >= (int)(v & 1u));
    return off;
}
// position of q-th set bit across 128-bit (w0..w3)
__device__ __forceinline__ int sel128(u32 w0, u32 w1, u32 w2, u32 w3, int q) {
    int base = 0;
    u32 cw = w0;
    int c = __popc(w0);
    if (q >= c) {
        q -= c; cw = w1; base = 32; c = __popc(w1);
        if (q >= c) {
            q -= c; cw = w2; base = 64; c = __popc(w2);
            if (q >= c) { q -= c; cw = w3; base = 96; }
        }
    }
    return base + sel_in_word(cw, q);
}

// ---------------- prep: C = (A + I)^T as 128-bit columns --------------------
__global__ void prep_kernel(const int* __restrict__ A)
{
    __shared__ u32 Brow[NTOT][4];
    const int tid  = threadIdx.x;
    const int lane = tid & 31;

    #pragma unroll
    for (int it = 0; it < 16; it++) {
        int i = it * 1024 + tid;               // i = n*128 + j
        u32 word = __ballot_sync(0xFFFFFFFFu, A[i] != 0);
        if (lane == 0) Brow[i >> 7][(i & 127) >> 5] = word;
    }
    __syncthreads();
    if (tid < NTOT) Brow[tid][tid >> 5] |= 1u << (tid & 31);   // + I
    __syncthreads();
    const int ww = tid >> 5;
    if (ww < 16) {
        int gr = ww >> 2, gc = ww & 3;
        u32 x = Brow[gr * 32 + lane][gc];
        x = transpose32(x, lane);
        g_C[(gc * 32 + lane) * 4 + gr] = x;    // C[j].word[gr]
    }
}

// ---------------- main ------------------------------------------------------
__global__ __launch_bounds__(NTH, 8)
void median_kernel(const float* __restrict__ xs, float* __restrict__ out)
{
    __shared__ u32 tile[NTOT * 5];         // cur  [row][cl] (stride 5)
    __shared__ u32 pvt [NTOT * 5];         // prev [row][cl] (INF if t==0)
    __shared__ u32 nxt [NTOT * 5];         // next [row][cl] (INF if t==T-1)
    __shared__ u32 skey[CPB * 132];        // sorted keys per channel
    __shared__ u32 Csm [NTOT * 4];         // C columns
    __shared__ u32 Psm [NTOT * PSTR];      // P[n][cl][r] at n*17 + cl*4 + r

    const int bid  = blockIdx.x;
    const int bt   = bid >> 3;             // frame
    const int cg   = bid & 7;              // channel quad
    const int t    = bt & (Tc - 1);
    const int tid  = threadIdx.x;
    const int lane = tid & 31;
    const int w    = tid >> 5;

    const bool hasPrev = (t > 0);
    const bool hasNext = (t < Tc - 1);

    // ---- phase 0: stage tiles + C ----
    {
        const uint4* b4 = (const uint4*)xs;        // frame = 1024 uint4
        const int off = tid * 8 + cg;
        uint4 v = b4[(size_t)bt * 1024 + off];
        tile[tid * 5 + 0] = f2u(__uint_as_float(v.x));
        tile[tid * 5 + 1] = f2u(__uint_as_float(v.y));
        tile[tid * 5 + 2] = f2u(__uint_as_float(v.z));
        tile[tid * 5 + 3] = f2u(__uint_as_float(v.w));
        uint4 p = make_uint4(~0u, ~0u, ~0u, ~0u), q = p;
        if (hasPrev) {
            uint4 x = b4[(size_t)(bt - 1) * 1024 + off];
            p = make_uint4(f2u(__uint_as_float(x.x)), f2u(__uint_as_float(x.y)),
                           f2u(__uint_as_float(x.z)), f2u(__uint_as_float(x.w)));
        }
        if (hasNext) {
            uint4 x = b4[(size_t)(bt + 1) * 1024 + off];
            q = make_uint4(f2u(__uint_as_float(x.x)), f2u(__uint_as_float(x.y)),
                           f2u(__uint_as_float(x.z)), f2u(__uint_as_float(x.w)));
        }
        pvt[tid * 5 + 0] = p.x; pvt[tid * 5 + 1] = p.y;
        pvt[tid * 5 + 2] = p.z; pvt[tid * 5 + 3] = p.w;
        nxt[tid * 5 + 0] = q.x; nxt[tid * 5 + 1] = q.y;
        nxt[tid * 5 + 2] = q.z; nxt[tid * 5 + 3] = q.w;
        ((uint4*)Csm)[tid] = ((const uint4*)g_C)[tid];
    }
    __syncthreads();

    // ---- phase 1: warp w sorts channel w, builds skey + P ----
    u32 k[4], xi[4];
    #pragma unroll
    for (int r = 0; r < 4; r++) {
        int p = r * 32 + lane;
        k[r]  = tile[p * 5 + w];
        xi[r] = (u32)p;
    }

    #pragma unroll
    for (int size = 2; size <= 128; size <<= 1) {
        #pragma unroll
        for (int stride = size >> 1; stride > 0; stride >>= 1) {
            if (stride >= 32) {
                int sr = stride >> 5;
                #pragma unroll
                for (int r = 0; r < 4; r++) {
                    if (!(r & sr)) {
                        int r2 = r | sr;
                        bool up = (((r * 32) & size) == 0);
                        if ((k[r] > k[r2]) == up) {
                            u32 tk = k[r]; k[r] = k[r2]; k[r2] = tk;
                            u32 tx = xi[r]; xi[r] = xi[r2]; xi[r2] = tx;
                        }
                    }
                }
            } else {
                #pragma unroll
                for (int r = 0; r < 4; r++) {
                    u32 p = (u32)(r * 32 + lane);
                    bool up    = ((p & (u32)size) == 0);
                    bool lower = ((lane & stride) == 0);
                    u32 pk = __shfl_xor_sync(0xFFFFFFFFu, k[r],  stride);
                    u32 px = __shfl_xor_sync(0xFFFFFFFFu, xi[r], stride);
                    bool take = (lower == up) ? (pk < k[r]) : (pk > k[r]);
                    if (take) { k[r] = pk; xi[r] = px; }
                }
            }
        }
    }

    #pragma unroll
    for (int r = 0; r < 4; r++)
        skey[w * 132 + r * 32 + lane] = k[r];

    // P: for pos block r, gather column C[xi[r]], bit-transpose per node-word
    #pragma unroll
    for (int r = 0; r < 4; r++) {
        uint4 col = ((const uint4*)Csm)[xi[r]];
        #pragma unroll
        for (int g = 0; g < 4; g++) {
            u32 x = (g == 0) ? col.x : (g == 1) ? col.y : (g == 2) ? col.z : col.w;
            x = transpose32(x, lane);          // lane -> node offset, bits -> pos
            Psm[(g * 32 + lane) * PSTR + w * 4 + r] = x;
        }
    }
    __syncthreads();

    // ---- phase 2: lane+warp = node; 5-candidate exact selection ----
    const int n = w * 32 + lane;
    u32 P[CPB][4];
    #pragma unroll
    for (int cl = 0; cl < CPB; cl++)
        #pragma unroll
        for (int r = 0; r < 4; r++)
            P[cl][r] = Psm[n * PSTR + cl * 4 + r];

    const int kpop = __popc(P[0][0]) + __popc(P[0][1])
                   + __popc(P[0][2]) + __popc(P[0][3]);
    const int e = (int)hasPrev + (int)hasNext;
    const int m = (kpop + e - 1) >> 1;

    float res[CPB];
    #pragma unroll
    for (int cl = 0; cl < CPB; cl++) {
        const u32 p  = pvt[n * 5 + cl];
        const u32 nx = nxt[n * 5 + cl];
        const u32* S = skey + cl * 132;

        // member order stats around the median (sentinels outside range)
        u32 x0 = 0u, x1 = 0u, x2 = 0xFFFFFFFFu;
        if (m >= 2)    x0 = S[sel128(P[cl][0], P[cl][1], P[cl][2], P[cl][3], m - 2)];
        if (m >= 1)    x1 = S[sel128(P[cl][0], P[cl][1], P[cl][2], P[cl][3], m - 1)];
        if (m < kpop)  x2 = S[sel128(P[cl][0], P[cl][1], P[cl][2], P[cl][3], m)];

        const int c2 = (int)(p < x2) + (int)(nx < x2);
        const int c1 = (int)(p < x1) + (int)(nx < x1);
        const int c0 = (int)(p < x0) + (int)(nx < x0);

        u32 ans;
        if (c2 == 0)      ans = x2;                 // rank(M[m])   = m
        else if (c1 == 1) ans = x1;                 // rank(M[m-1]) = m
        else if (c0 == 2) ans = x0;                 // rank(M[m-2]) = m
        else if (c1 == 0) ans = (nx < p) ? nx : p;  // temporal in (M[m-1],M[m])
        else              ans = (p <= nx) ? nx : p; // temporal in (M[m-2],M[m-1])
        res[cl] = u2f(ans);
    }

    ((float4*)(out + (size_t)bt * (NTOT * Dc) + n * Dc + cg * 4))[0] =
        make_float4(res[0], res[1], res[2], res[3]);
}

extern "C" void kernel_launch(void* const* d_in, const int* in_sizes, int n_in,
                              void* d_out, int out_size)
{
    const float* xs  = (const float*)d_in[0];
    const int*   A   = (const int*)d_in[1];
    float*       out = (float*)d_out;
    (void)in_sizes; (void)n_in; (void)out_size;

    cudaFuncSetAttribute(median_kernel,
                         cudaFuncAttributePreferredSharedMemoryCarveout, 100);
    prep_kernel<<<1, 1024>>>(A);
    median_kernel<<<Bc * Tc * 8, NTH>>>(xs, out);
}

// round 16
// speedup vs baseline: 1.5654x; 1.2012x over previous
#include <cuda_runtime.h>

// MedianFilter: xs [B=4,T=32,N=128,D=32] f32, A [1,128,128] i32.
// Per (b,t,n,d): lower median over {prev-self (t>0), next-self (t<T-1),
//   xs[b,t,j,d] for j with (A+I)[n][j]!=0}.
//
// Exact, search-free selection:
//  - warp per channel: BLOCKED bitonic sort of 128 frame values (4 consecutive
//    elements per lane => strides 1-2 are in-thread, only strides >=4 shuffle)
//  - per node: P[n] = 128-bit membership mask permuted into sorted order
//    (warp-shuffle 32x32 bit transposes of C = (A+I)^T columns)
//  - median: order-stats M[m-2..m] via register select-bit on P; prev/next
//    resolved by the 5-candidate rank rule. No value searches.

#define Bc 4
#define Tc 32
#define NTOT 128
#define Dc 32
#define NTH 128          // 4 warps per block
#define CPB 4            // channels per block
#define PSTR 17          // P row stride in words (odd -> conflict-free)

typedef unsigned u32;

__device__ u32 g_C[NTOT * 4];   // C[j].word[g]: bit n' = (A+I)[g*32+n'][j] != 0

__device__ __forceinline__ u32 f2u(float f) {
    u32 s = __float_as_uint(f);
    return s ^ ((u32)((int)s >> 31) | 0x80000000u);
}
__device__ __forceinline__ float u2f(u32 u) {
    u32 s = (u & 0x80000000u) ? (u ^ 0x80000000u) : ~u;
    return __uint_as_float(s);
}

// 32x32 bit-matrix transpose across a warp (lane = row, bits = cols)
__device__ __forceinline__ u32 transpose32(u32 x, int lane) {
    u32 y;
#define TSTEP(J, M)                                              \
    y = __shfl_xor_sync(0xFFFFFFFFu, x, J);                      \
    x = (lane & J) ? ((x & ~(M)) | ((y >> J) & (M)))             \
                   : ((x & (M)) | ((y & (M)) << J));
    TSTEP(16, 0x0000FFFFu)
    TSTEP(8,  0x00FF00FFu)
    TSTEP(4,  0x0F0F0F0Fu)
    TSTEP(2,  0x33333333u)
    TSTEP(1,  0x55555555u)
#undef TSTEP
    return x;
}

// position of q-th (0-based) set bit of v (q < popc(v))
__device__ __forceinline__ int sel_in_word(u32 v, int q) {
    int off = 0;
    int c;
    c = __popc(v & 0xFFFFu); if (q >= c) { q -= c; v >>= 16; off += 16; }
    c = __popc(v & 0xFFu);   if (q >= c) { q -= c; v >>= 8;  off += 8; }
    c = __popc(v & 0xFu);    if (q >= c) { q -= c; v >>= 4;  off += 4; }
    c = __popc(v & 0x3u);    if (q >= c) { q -= c; v >>= 2;  off += 2; }
    off += (int)(q >= (int)(v & 1u));
    return off;
}
// position of q-th set bit across 128-bit (w0..w3)
__device__ __forceinline__ int sel128(u32 w0, u32 w1, u32 w2, u32 w3, int q) {
    int base = 0;
    u32 cw = w0;
    int c = __popc(w0);
    if (q >= c) {
        q -= c; cw = w1; base = 32; c = __popc(w1);
        if (q >= c) {
            q -= c; cw = w2; base = 64; c = __popc(w2);
            if (q >= c) { q -= c; cw = w3; base = 96; }
        }
    }
    return base + sel_in_word(cw, q);
}

// ---------------- prep: C = (A + I)^T, wide (4 blocks x 1024) ---------------
__global__ void prep_kernel(const int* __restrict__ A)
{
    const int g    = blockIdx.x;          // node word group 0..3
    const int tid  = threadIdx.x;
    const int w    = tid >> 5;            // column quad 0..31
    const int lane = tid & 31;            // node offset within group

    int4 v = ((const int4*)A)[(g * 32 + lane) * 32 + w];   // A[g*32+lane][4w..4w+3]
    u32 b0 = __ballot_sync(0xFFFFFFFFu, v.x != 0);
    u32 b1 = __ballot_sync(0xFFFFFFFFu, v.y != 0);
    u32 b2 = __ballot_sync(0xFFFFFFFFu, v.z != 0);
    u32 b3 = __ballot_sync(0xFFFFFFFFu, v.w != 0);
    if (lane == 0) {
        u32 arr[4] = {b0, b1, b2, b3};
        #pragma unroll
        for (int jj = 0; jj < 4; jj++) {
            int j = w * 4 + jj;
            if ((j >> 5) == g) arr[jj] |= 1u << (j & 31);   // + I
            g_C[j * 4 + g] = arr[jj];
        }
    }
}

// in-thread compare-exchange (indices a < b); ascending if asc
#define CSW(a, b, asc)                                                     \
    {                                                                      \
        bool sw_ = (asc) ? (k[a] > k[b]) : (k[a] < k[b]);                  \
        if (sw_) {                                                         \
            u32 tk_ = k[a]; k[a] = k[b]; k[b] = tk_;                       \
            u32 tx_ = xi[a]; xi[a] = xi[b]; xi[b] = tx_;                   \
        }                                                                  \
    }

// ---------------- main ------------------------------------------------------
__global__ __launch_bounds__(NTH, 8)
void median_kernel(const float* __restrict__ xs, float* __restrict__ out)
{
    __shared__ u32 tile[CPB * 132];        // cur  [cl][row] (blocked sort load)
    __shared__ u32 pvt [NTOT * 5];         // prev [row][cl] (INF if t==0)
    __shared__ u32 nxt [NTOT * 5];         // next [row][cl] (INF if t==T-1)
    __shared__ u32 skey[CPB * 132];        // sorted keys per channel
    __shared__ u32 xism[CPB * 32];         // sorted row indices (packed bytes)
    __shared__ u32 Csm [NTOT * 4];         // C columns
    __shared__ u32 Psm [NTOT * PSTR];      // P[n][cl][r] at n*17 + cl*4 + r

    const int bid  = blockIdx.x;
    const int bt   = bid >> 3;             // frame
    const int cg   = bid & 7;              // channel quad
    const int t    = bt & (Tc - 1);
    const int tid  = threadIdx.x;
    const int lane = tid & 31;
    const int w    = tid >> 5;

    const bool hasPrev = (t > 0);
    const bool hasNext = (t < Tc - 1);

    // ---- phase 0: stage tiles + C ----
    {
        const uint4* b4 = (const uint4*)xs;        // frame = 1024 uint4
        const int off = tid * 8 + cg;              // row tid, channel quad cg
        uint4 v = b4[(size_t)bt * 1024 + off];
        tile[0 * 132 + tid] = f2u(__uint_as_float(v.x));
        tile[1 * 132 + tid] = f2u(__uint_as_float(v.y));
        tile[2 * 132 + tid] = f2u(__uint_as_float(v.z));
        tile[3 * 132 + tid] = f2u(__uint_as_float(v.w));
        uint4 p = make_uint4(~0u, ~0u, ~0u, ~0u), q = p;
        if (hasPrev) {
            uint4 x = b4[(size_t)(bt - 1) * 1024 + off];
            p = make_uint4(f2u(__uint_as_float(x.x)), f2u(__uint_as_float(x.y)),
                           f2u(__uint_as_float(x.z)), f2u(__uint_as_float(x.w)));
        }
        if (hasNext) {
            uint4 x = b4[(size_t)(bt + 1) * 1024 + off];
            q = make_uint4(f2u(__uint_as_float(x.x)), f2u(__uint_as_float(x.y)),
                           f2u(__uint_as_float(x.z)), f2u(__uint_as_float(x.w)));
        }
        pvt[tid * 5 + 0] = p.x; pvt[tid * 5 + 1] = p.y;
        pvt[tid * 5 + 2] = p.z; pvt[tid * 5 + 3] = p.w;
        nxt[tid * 5 + 0] = q.x; nxt[tid * 5 + 1] = q.y;
        nxt[tid * 5 + 2] = q.z; nxt[tid * 5 + 3] = q.w;
        ((uint4*)Csm)[tid] = ((const uint4*)g_C)[tid];
    }
    __syncthreads();

    // ---- phase 1: warp w sorts channel w (blocked layout), builds P -------
    // element index p = lane*4 + r  (4 consecutive per lane)
    u32 k[4], xi[4];
    {
        uint4 kv = ((const uint4*)(tile + w * 132))[lane];
        k[0] = kv.x; k[1] = kv.y; k[2] = kv.z; k[3] = kv.w;
        xi[0] = (u32)(lane * 4 + 0); xi[1] = (u32)(lane * 4 + 1);
        xi[2] = (u32)(lane * 4 + 2); xi[3] = (u32)(lane * 4 + 3);
    }

    // size 2: dir by (p & 2) -> pair (0,1) asc, (2,3) desc
    CSW(0, 1, true)
    CSW(2, 3, false)
    // size 4: dir = ((p & 4) == 0) = ((lane & 1) == 0)
    {
        bool a4 = (lane & 1) == 0;
        CSW(0, 2, a4) CSW(1, 3, a4) CSW(0, 1, a4) CSW(2, 3, a4)
    }
    // sizes 8..128: cross-lane strides >=4, then in-thread strides 2,1
    #pragma unroll
    for (int sz = 8; sz <= 128; sz <<= 1) {
        bool asc = (lane & (sz >> 2)) == 0;
        #pragma unroll
        for (int d = sz >> 1; d >= 4; d >>= 1) {
            int dd = d >> 2;                       // lane distance
            bool keepmin = (((lane & dd) == 0) == asc);
            #pragma unroll
            for (int r = 0; r < 4; r++) {
                u32 pk = __shfl_xor_sync(0xFFFFFFFFu, k[r],  dd);
                u32 px = __shfl_xor_sync(0xFFFFFFFFu, xi[r], dd);
                bool less = pk < k[r], grt = pk > k[r];
                bool take = keepmin ? less : grt;
                if (take) { k[r] = pk; xi[r] = px; }
            }
        }
        CSW(0, 2, asc) CSW(1, 3, asc) CSW(0, 1, asc) CSW(2, 3, asc)
    }

    ((uint4*)(skey + w * 132))[lane] = make_uint4(k[0], k[1], k[2], k[3]);
    xism[w * 32 + lane] = xi[0] | (xi[1] << 8) | (xi[2] << 16) | (xi[3] << 24);
    __syncwarp();

    // P: for pos word rp, gather column C[xi[pos]], bit-transpose per node-word
    #pragma unroll
    for (int rp = 0; rp < 4; rp++) {
        u32 xw = xism[w * 32 + rp * 8 + (lane >> 2)];
        u32 xv = (xw >> ((lane & 3) * 8)) & 255u;      // row at pos rp*32+lane
        uint4 col = ((const uint4*)Csm)[xv];
        #pragma unroll
        for (int g = 0; g < 4; g++) {
            u32 x = (g == 0) ? col.x : (g == 1) ? col.y : (g == 2) ? col.z : col.w;
            x = transpose32(x, lane);          // lane -> node offset, bits -> pos
            Psm[(g * 32 + lane) * PSTR + w * 4 + rp] = x;
        }
    }
    __syncthreads();

    // ---- phase 2: lane+warp = node; 5-candidate exact selection ----
    const int n = w * 32 + lane;
    u32 P[CPB][4];
    #pragma unroll
    for (int cl = 0; cl < CPB; cl++)
        #pragma unroll
        for (int r = 0; r < 4; r++)
            P[cl][r] = Psm[n * PSTR + cl * 4 + r];

    const int kpop = __popc(P[0][0]) + __popc(P[0][1])
                   + __popc(P[0][2]) + __popc(P[0][3]);
    const int e = (int)hasPrev + (int)hasNext;
    const int m = (kpop + e - 1) >> 1;

    float res[CPB];
    #pragma unroll
    for (int cl = 0; cl < CPB; cl++) {
        const u32 p  = pvt[n * 5 + cl];
        const u32 nx = nxt[n * 5 + cl];
        const u32* S = skey + cl * 132;

        // member order stats around the median (sentinels outside range)
        u32 x0 = 0u, x1 = 0u, x2 = 0xFFFFFFFFu;
        if (m >= 2)    x0 = S[sel128(P[cl][0], P[cl][1], P[cl][2], P[cl][3], m - 2)];
        if (m >= 1)    x1 = S[sel128(P[cl][0], P[cl][1], P[cl][2], P[cl][3], m - 1)];
        if (m < kpop)  x2 = S[sel128(P[cl][0], P[cl][1], P[cl][2], P[cl][3], m)];

        const int c2 = (int)(p < x2) + (int)(nx < x2);
        const int c1 = (int)(p < x1) + (int)(nx < x1);
        const int c0 = (int)(p < x0) + (int)(nx < x0);

        u32 ans;
        if (c2 == 0)      ans = x2;                 // rank(M[m])   = m
        else if (c1 == 1) ans = x1;                 // rank(M[m-1]) = m
        else if (c0 == 2) ans = x0;                 // rank(M[m-2]) = m
        else if (c1 == 0) ans = (nx < p) ? nx : p;  // temporal in (M[m-1],M[m])
        else              ans = (p <= nx) ? nx : p; // temporal in (M[m-2],M[m-1])
        res[cl] = u2f(ans);
    }

    ((float4*)(out + (size_t)bt * (NTOT * Dc) + n * Dc + cg * 4))[0] =
        make_float4(res[0], res[1], res[2], res[3]);
}

extern "C" void kernel_launch(void* const* d_in, const int* in_sizes, int n_in,
                              void* d_out, int out_size)
{
    const float* xs  = (const float*)d_in[0];
    const int*   A   = (const int*)d_in[1];
    float*       out = (float*)d_out;
    (void)in_sizes; (void)n_in; (void)out_size;

    cudaFuncSetAttribute(median_kernel,
                         cudaFuncAttributePreferredSharedMemoryCarveout, 100);
    prep_kernel<<<4, 1024>>>(A);
    median_kernel<<<Bc * Tc * 8, NTH>>>(xs, out);
}